// round 11
// baseline (speedup 1.0000x reference)
#include <cuda_runtime.h>
#include <math.h>

#define T    2048
#define F    1024
#define NB   64          // total batch
#define HB   32          // half batch
#define KSEL 20

// scratch (no allocs allowed)
__device__ float g_mags[NB * T];
__device__ int   g_idx[NB * KSEL];

// -------- kernel 1: per-(b,t) L2 norm over feature dim --------
// one warp per row; 8 float4 loads per lane, fully coalesced. HBM-bound
// at ~6.9 TB/s (86% of spec) — measured roofline.
__global__ void mag_kernel(const float* __restrict__ feat) {
    int warp = (blockIdx.x * blockDim.x + threadIdx.x) >> 5;  // 0 .. 64*2048-1
    int lane = threadIdx.x & 31;
    const float4* row = (const float4*)(feat + (size_t)warp * F);
    float s = 0.f;
#pragma unroll
    for (int i = 0; i < 8; i++) {
        float4 v = row[lane + i * 32];
        s += v.x * v.x + v.y * v.y + v.z * v.z + v.w * v.w;
    }
#pragma unroll
    for (int o = 16; o; o >>= 1) s += __shfl_xor_sync(0xffffffffu, s, o);
    if (lane == 0) g_mags[warp] = sqrtf(s);
    // PDL: let the topk kernel begin launching while this grid drains
    cudaTriggerProgrammaticLaunchCompletion();
}

// -------- kernel 2: top-K + score mean (64 blocks, PDL secondary) ---------
// Mask loads (independent of mags) run BEFORE the grid-dependency sync, so
// they overlap mag_kernel's tail. Warp-local top-20 + single-warp 8-way
// merge; one __syncthreads. Stable (value desc, index asc) tie-break.
__global__ void __launch_bounds__(256)
topk_kernel(const float* __restrict__ scores,
            const float* __restrict__ mask_abn,
            const float* __restrict__ mask_nor,
            float* __restrict__ out) {
    __shared__ float s_wv[8][21];
    __shared__ int   s_wi[8][21];

    int b = blockIdx.x;
    int tid = threadIdx.x;
    int lane = tid & 31;
    int wid = tid >> 5;

    int batch;
    const float* mask;
    if (b < HB) { batch = HB + b; mask = mask_abn + (size_t)b * T; }
    else        { batch = b - HB; mask = mask_nor + (size_t)(b - HB) * T; }

    // ---- prologue (no dependence on mag_kernel): dropout factors ----
    const float inv = 1.0f / 0.9f;   // 1/(1-P)
    float d[8];
#pragma unroll
    for (int j = 0; j < 8; j++) {
        int t = wid * 256 + j * 32 + lane;    // warp owns contiguous 256
        d[j] = (mask[t] > 0.1f) ? inv : 0.0f;
    }

    // ---- wait for mag_kernel's stores to be visible ----
    cudaGridDependencySynchronize();

    float v[8];
#pragma unroll
    for (int j = 0; j < 8; j++) {
        int t = wid * 256 + j * 32 + lane;
        v[j] = g_mags[batch * T + t] * d[j];
    }

    // 20 warp-local rounds, no block syncs
    for (int k = 0; k < KSEL; k++) {
        float bv = -1.0f; int bi = 1 << 30;
#pragma unroll
        for (int j = 0; j < 8; j++) {
            if (v[j] > bv) { bv = v[j]; bi = wid * 256 + j * 32 + lane; }
        }
#pragma unroll
        for (int o = 16; o; o >>= 1) {
            float ov = __shfl_xor_sync(0xffffffffu, bv, o);
            int   oi = __shfl_xor_sync(0xffffffffu, bi, o);
            if (ov > bv || (ov == bv && oi < bi)) { bv = ov; bi = oi; }
        }
        if (lane == 0) { s_wv[wid][k] = bv; s_wi[wid][k] = bi; }
        int local = bi - wid * 256;           // remove winner from registers
        if ((local & 31) == lane) v[local >> 5] = -1.0f;
    }
    if (lane == 0) { s_wv[wid][20] = -2.0f; s_wi[wid][20] = 1 << 30; }
    __syncthreads();

    // warp 0: merge 8 descending lists of 20 (lanes 0..7 hold list heads)
    if (wid == 0) {
        int   p  = 0;
        float hv = (lane < 8) ? s_wv[lane][0] : -3.0f;
        int   hi = (lane < 8) ? s_wi[lane][0] : (1 << 30);
        int my_idx = 0;
        for (int k = 0; k < KSEL; k++) {
            float fv = hv; int fi = hi;
#pragma unroll
            for (int o = 4; o; o >>= 1) {
                float ov = __shfl_xor_sync(0xffffffffu, fv, o);
                int   oi = __shfl_xor_sync(0xffffffffu, fi, o);
                if (ov > fv || (ov == fv && oi < fi)) { fv = ov; fi = oi; }
            }
            fi = __shfl_sync(0xffffffffu, fi, 0);       // broadcast winner
            if (lane == k) my_idx = fi;
            if (lane < 8 && hi == fi) {                 // advance that list
                p++; hv = s_wv[lane][p]; hi = s_wi[lane][p];
            }
        }
        // indices + score mean (one parallel load pass)
        float sc = 0.f;
        if (lane < KSEL) {
            g_idx[b * KSEL + lane] = my_idx;
            sc = scores[(size_t)batch * T + my_idx];
        }
#pragma unroll
        for (int o = 16; o; o >>= 1) sc += __shfl_xor_sync(0xffffffffu, sc, o);
        if (lane == 0) out[b] = sc / (float)KSEL;   // [0,32)=abn, [32,64)=nor
    }
    cudaTriggerProgrammaticLaunchCompletion();
}

// -------- kernel 3: gather, grid-stride, 4 float4 per thread (PDL) --------
#define GTHREADS (320 * 256)

__global__ void __launch_bounds__(256)
gather_kernel(const float* __restrict__ feat,
              float* __restrict__ out) {
    int gid = blockIdx.x * 256 + threadIdx.x;
    cudaGridDependencySynchronize();     // wait for g_idx from topk_kernel

    const float4* srcp[4];
    int rows[4];
    int cs[4];
#pragma unroll
    for (int i = 0; i < 4; i++) {
        int e   = gid + i * GTHREADS;    // element id
        int row = e >> 8;                // / 256 float4s per row
        int c   = e & 255;
        int orow = row / KSEL;           // 0..63 (abn rows first)
        int k    = row % KSEL;
        int batch = (orow < HB) ? (HB + orow) : (orow - HB);
        int idx = g_idx[orow * KSEL + k];
        srcp[i] = (const float4*)(feat + ((size_t)batch * T + idx) * F) + c;
        rows[i] = row; cs[i] = c;
    }
    // batched loads (MLP=4), then stores
    float4 vbuf[4];
#pragma unroll
    for (int i = 0; i < 4; i++) vbuf[i] = *srcp[i];
    float4* dst = (float4*)(out + 64);
#pragma unroll
    for (int i = 0; i < 4; i++) dst[(size_t)rows[i] * 256 + cs[i]] = vbuf[i];
}

extern "C" void kernel_launch(void* const* d_in, const int* in_sizes, int n_in,
                              void* d_out, int out_size) {
    const float* feat   = (const float*)d_in[0];
    const float* scores = (const float*)d_in[1];
    const float* mabn   = (const float*)d_in[2];
    const float* mnor   = (const float*)d_in[3];
    float* out = (float*)d_out;

    // 1) mag (primary)
    mag_kernel<<<(NB * T) / 8, 256>>>(feat);

    // 2) topk as PDL secondary of mag
    {
        cudaLaunchConfig_t cfg = {};
        cfg.gridDim  = dim3(NB);
        cfg.blockDim = dim3(256);
        cudaLaunchAttribute attr[1];
        attr[0].id = cudaLaunchAttributeProgrammaticStreamSerialization;
        attr[0].val.programmaticStreamSerializationAllowed = 1;
        cfg.attrs = attr;
        cfg.numAttrs = 1;
        cudaLaunchKernelEx(&cfg, topk_kernel, scores, mabn, mnor, out);
    }

    // 3) gather as PDL secondary of topk
    {
        cudaLaunchConfig_t cfg = {};
        cfg.gridDim  = dim3(320);
        cfg.blockDim = dim3(256);
        cudaLaunchAttribute attr[1];
        attr[0].id = cudaLaunchAttributeProgrammaticStreamSerialization;
        attr[0].val.programmaticStreamSerializationAllowed = 1;
        cfg.attrs = attr;
        cfg.numAttrs = 1;
        cudaLaunchKernelEx(&cfg, gather_kernel, feat, out);
    }
}